// round 10
// baseline (speedup 1.0000x reference)
#include <cuda_runtime.h>

#define J     24
#define TPB   128
#define PITCH 33   // staging row pitch (odd -> conflict-free scalar STS)

__global__ __launch_bounds__(TPB, 9) void fk_kernel(
    const float* __restrict__ angles,   // [B, 24]
    const float* __restrict__ Torg,     // [24, 4, 4]
    const float* __restrict__ axes,     // [24, 3] unit axes
    float* __restrict__ out,            // [B, 75]
    int B)
{
    // Per-joint derived constants: {wx,wy,wz,_, bx,by,bz,_}
    __shared__ __align__(16) float kjc[J][8];
    // Phase staging: row = thread (element), 32 local cols used, pitch 33.
    __shared__ float sbuf[TPB * PITCH];

    const int tid  = threadIdx.x;
    const int warp = tid >> 5;
    const int lane = tid & 31;

    // ---- Warp 0: shuffle-scan of cumulative fixed rotations ----
    // C_j = Q_0 ... Q_j ;  w_j = C_j u_j ;  b_j = C_{j-1} t_j.
    if (warp == 0) {
        float m[9];
        float ax = 0.f, ay = 0.f, az = 0.f;
        float ux = 0.f, uy = 0.f, uz = 0.f;
        m[0]=1.f; m[1]=0.f; m[2]=0.f;
        m[3]=0.f; m[4]=1.f; m[5]=0.f;
        m[6]=0.f; m[7]=0.f; m[8]=1.f;
        if (lane < J) {
            const float* t = Torg + lane * 16;
            m[0]=t[0]; m[1]=t[1]; m[2]=t[2];   ax=t[3];
            m[3]=t[4]; m[4]=t[5]; m[5]=t[6];   ay=t[7];
            m[6]=t[8]; m[7]=t[9]; m[8]=t[10];  az=t[11];
            ux = axes[lane*3+0]; uy = axes[lane*3+1]; uz = axes[lane*3+2];
        }
        #pragma unroll
        for (int d = 1; d < J; d <<= 1) {          // inclusive Kogge-Stone
            float L[9];
            #pragma unroll
            for (int k = 0; k < 9; ++k)
                L[k] = __shfl_up_sync(0xffffffffu, m[k], d);
            if (lane >= d) {
                float n[9];
                #pragma unroll
                for (int r = 0; r < 3; ++r)
                    #pragma unroll
                    for (int c = 0; c < 3; ++c)
                        n[r*3+c] = L[r*3+0]*m[0*3+c] + L[r*3+1]*m[1*3+c]
                                 + L[r*3+2]*m[2*3+c];
                #pragma unroll
                for (int k = 0; k < 9; ++k) m[k] = n[k];
            }
        }
        float E[9];                                 // exclusive prefix
        #pragma unroll
        for (int k = 0; k < 9; ++k)
            E[k] = __shfl_up_sync(0xffffffffu, m[k], 1);
        if (lane == 0) {
            E[0]=1.f; E[1]=0.f; E[2]=0.f;
            E[3]=0.f; E[4]=1.f; E[5]=0.f;
            E[6]=0.f; E[7]=0.f; E[8]=1.f;
        }
        if (lane < J) {
            kjc[lane][0] = m[0]*ux + m[1]*uy + m[2]*uz;   // w = C_j u
            kjc[lane][1] = m[3]*ux + m[4]*uy + m[5]*uz;
            kjc[lane][2] = m[6]*ux + m[7]*uy + m[8]*uz;
            kjc[lane][3] = 0.f;
            kjc[lane][4] = E[0]*ax + E[1]*ay + E[2]*az;   // b = C_{j-1} t
            kjc[lane][5] = E[3]*ax + E[4]*ay + E[5]*az;
            kjc[lane][6] = E[6]*ax + E[7]*ay + E[8]*az;
            kjc[lane][7] = 0.f;
        }
    }

    const int base = blockIdx.x * TPB;
    const int e = base + tid;
    const bool active = (e < B);
    const int nvalid = min(TPB, B - base);
    float* gout = out + (size_t)base * 75;

    // All 24 angles: 6 LDG.128 (row start e*96 B is 16B aligned).
    float a[J];
    if (active) {
        const float4* ap = reinterpret_cast<const float4*>(angles + (size_t)e * J);
        #pragma unroll
        for (int q = 0; q < J / 4; ++q) {
            float4 v = __ldg(ap + q);
            a[4*q+0] = v.x; a[4*q+1] = v.y; a[4*q+2] = v.z; a[4*q+3] = v.w;
        }
    }

    // State: quaternion P (w,x,y,z) and position p.
    float Pw = 1.f, Px = 0.f, Py = 0.f, Pz = 0.f;
    float px = 0.f, py = 0.f, pz = 0.f;
    float* so = sbuf + tid * PITCH;
    const float4* kc = reinterpret_cast<const float4*>(kjc);

    // One joint step: advance position, then quaternion (skip quat at j=23).
    #define STEP(j, ang)                                                      \
    {                                                                         \
        const float4 wv = kc[2*(j)];                                          \
        const float4 bv = kc[2*(j) + 1];                                      \
        const float tx = Py*bv.z - Pz*bv.y;                                   \
        const float ty = Pz*bv.x - Px*bv.z;                                   \
        const float tz = Px*bv.y - Py*bv.x;                                   \
        const float w2 = Pw + Pw;                                             \
        const float ox = Py*tz - Pz*ty;                                       \
        const float oy = Pz*tx - Px*tz;                                       \
        const float oz = Px*ty - Py*tx;                                       \
        px += bv.x + w2*tx + 2.f*ox;                                          \
        py += bv.y + w2*ty + 2.f*oy;                                          \
        pz += bv.z + w2*tz + 2.f*oz;                                          \
        if ((j) < J - 1) {                                                    \
            float s_, c_;                                                     \
            __sincosf(0.5f * (ang), &s_, &c_);                                \
            const float qx = s_*wv.x, qy = s_*wv.y, qz = s_*wv.z;             \
            const float nw = Pw*c_ - Px*qx - Py*qy - Pz*qz;                   \
            const float nx = Pw*qx + Px*c_ + Py*qz - Pz*qy;                   \
            const float ny = Pw*qy - Px*qz + Py*c_ + Pz*qx;                   \
            const float nz = Pw*qz + Px*qy - Py*qx + Pz*c_;                   \
            Pw = nw; Px = nx; Py = ny; Pz = nz;                               \
        }                                                                     \
    }

    // Flush 32 cols [off, off+32) for all rows: warp w, iter k -> row w+4k,
    // col = lane. Immediate-offset LDS/STG, predicated on row validity.
    #define FLUSH32(off)                                                      \
    {                                                                         \
        const float* src = sbuf + warp * PITCH + lane;                        \
        float* dst = gout + warp * 75 + (off) + lane;                         \
        _Pragma("unroll")                                                     \
        for (int k = 0; k < 32; ++k)                                          \
            if (warp + 4*k < nvalid) dst[k*4*75] = src[k*4*PITCH];            \
    }

    __syncthreads();   // kjc ready

    // ---- Phase 0: cols [0,32) = base(0..2) + j0..8 full + j9 (px,py) ----
    if (active) {
        so[0] = 0.f; so[1] = 0.f; so[2] = 0.f;
        #pragma unroll
        for (int j = 0; j <= 8; ++j) {
            STEP(j, a[j]);
            so[3 + 3*j + 0] = px; so[3 + 3*j + 1] = py; so[3 + 3*j + 2] = pz;
        }
        STEP(9, a[9]);
        so[30] = px; so[31] = py;          // col 32 (pz) deferred
    }
    __syncthreads();
    FLUSH32(0);
    __syncthreads();

    // ---- Phase 1: cols [32,64) = j9.pz + j10..19 full + j20 (px) ----
    if (active) {
        so[0] = pz;                        // col 32
        #pragma unroll
        for (int j = 10; j <= 19; ++j) {
            STEP(j, a[j]);
            const int lc = 3 + 3*j - 32;
            so[lc] = px; so[lc+1] = py; so[lc+2] = pz;
        }
        STEP(20, a[20]);
        so[31] = px;                       // col 63; cols 64,65 deferred
    }
    __syncthreads();
    FLUSH32(32);
    __syncthreads();

    // ---- Phase 2: cols [64,75) = j20 (py,pz) + j21..23 full (11 cols) ----
    if (active) {
        so[0] = py; so[1] = pz;            // cols 64, 65
        #pragma unroll
        for (int j = 21; j <= 23; ++j) {
            STEP(j, a[j]);
            const int lc = 3 + 3*j - 64;
            so[lc] = px; so[lc+1] = py; so[lc+2] = pz;
        }
    }
    __syncthreads();
    // Flush 11 cols [64,75): lanes 0..10 active.
    if (lane < 11) {
        const float* src = sbuf + warp * PITCH + lane;
        float* dst = gout + warp * 75 + 64 + lane;
        #pragma unroll
        for (int k = 0; k < 32; ++k)
            if (warp + 4*k < nvalid) dst[k*4*75] = src[k*4*PITCH];
    }

    #undef STEP
    #undef FLUSH32
}

extern "C" void kernel_launch(void* const* d_in, const int* in_sizes, int n_in,
                              void* d_out, int out_size) {
    const float* angles = (const float*)d_in[0];   // [B, 24]
    const float* Torg   = (const float*)d_in[1];   // [24, 4, 4]
    const float* axes   = (const float*)d_in[2];   // [24, 3]
    float* out = (float*)d_out;                    // [B, 75]

    const int B = in_sizes[0] / J;
    const int blocks = (B + TPB - 1) / TPB;
    fk_kernel<<<blocks, TPB>>>(angles, Torg, axes, out, B);
}

// round 11
// speedup vs baseline: 1.1139x; 1.1139x over previous
#include <cuda_runtime.h>

#define J     24
#define TPB   128
#define SW    33            // staging pitch (odd -> conflict-free flush LDS)
#define WSTG  (32 * SW)     // floats per warp staging slab

__global__ __launch_bounds__(TPB, 9) void fk_kernel(
    const float* __restrict__ angles,   // [B, 24]
    const float* __restrict__ Torg,     // [24, 4, 4]
    const float* __restrict__ axes,     // [24, 3] unit axes
    float* __restrict__ out,            // [B, 75]
    int B)
{
    // Per-joint derived constants: {wx,wy,wz,_, bx,by,bz,_}
    __shared__ __align__(16) float kjc[J][8];
    // Warp-private column-major staging: (row=lane, col=lc) at lc*SW + lane.
    __shared__ float sbuf[(TPB / 32) * WSTG];   // 16.9 KB

    const int tid  = threadIdx.x;
    const int warp = tid >> 5;
    const int lane = tid & 31;

    // ---- Warp 0: shuffle-scan of cumulative fixed rotations ----
    // C_j = Q_0 ... Q_j ;  w_j = C_j u_j ;  b_j = C_{j-1} t_j.
    if (warp == 0) {
        float m[9];
        float ax = 0.f, ay = 0.f, az = 0.f;
        float ux = 0.f, uy = 0.f, uz = 0.f;
        m[0]=1.f; m[1]=0.f; m[2]=0.f;
        m[3]=0.f; m[4]=1.f; m[5]=0.f;
        m[6]=0.f; m[7]=0.f; m[8]=1.f;
        if (lane < J) {
            const float* t = Torg + lane * 16;
            m[0]=t[0]; m[1]=t[1]; m[2]=t[2];   ax=t[3];
            m[3]=t[4]; m[4]=t[5]; m[5]=t[6];   ay=t[7];
            m[6]=t[8]; m[7]=t[9]; m[8]=t[10];  az=t[11];
            ux = axes[lane*3+0]; uy = axes[lane*3+1]; uz = axes[lane*3+2];
        }
        #pragma unroll
        for (int d = 1; d < J; d <<= 1) {          // inclusive Kogge-Stone
            float L[9];
            #pragma unroll
            for (int k = 0; k < 9; ++k)
                L[k] = __shfl_up_sync(0xffffffffu, m[k], d);
            if (lane >= d) {
                float n[9];
                #pragma unroll
                for (int r = 0; r < 3; ++r)
                    #pragma unroll
                    for (int c = 0; c < 3; ++c)
                        n[r*3+c] = L[r*3+0]*m[0*3+c] + L[r*3+1]*m[1*3+c]
                                 + L[r*3+2]*m[2*3+c];
                #pragma unroll
                for (int k = 0; k < 9; ++k) m[k] = n[k];
            }
        }
        float E[9];                                 // exclusive prefix
        #pragma unroll
        for (int k = 0; k < 9; ++k)
            E[k] = __shfl_up_sync(0xffffffffu, m[k], 1);
        if (lane == 0) {
            E[0]=1.f; E[1]=0.f; E[2]=0.f;
            E[3]=0.f; E[4]=1.f; E[5]=0.f;
            E[6]=0.f; E[7]=0.f; E[8]=1.f;
        }
        if (lane < J) {
            kjc[lane][0] = m[0]*ux + m[1]*uy + m[2]*uz;   // w = C_j u
            kjc[lane][1] = m[3]*ux + m[4]*uy + m[5]*uz;
            kjc[lane][2] = m[6]*ux + m[7]*uy + m[8]*uz;
            kjc[lane][3] = 0.f;
            kjc[lane][4] = E[0]*ax + E[1]*ay + E[2]*az;   // b = C_{j-1} t
            kjc[lane][5] = E[3]*ax + E[4]*ay + E[5]*az;
            kjc[lane][6] = E[6]*ax + E[7]*ay + E[8]*az;
            kjc[lane][7] = 0.f;
        }
    }

    const int base = blockIdx.x * TPB;
    const int e = base + tid;
    const bool active = (e < B);
    const int nvalid = min(TPB, B - base);
    const bool full = (nvalid == TPB);
    float* gout = out + (size_t)base * 75;

    // All 24 angles: 6 LDG.128 (row start e*96 B is 16B aligned).
    float a[J];
    if (active) {
        const float4* ap = reinterpret_cast<const float4*>(angles + (size_t)e * J);
        #pragma unroll
        for (int q = 0; q < J / 4; ++q) {
            float4 v = __ldg(ap + q);
            a[4*q+0] = v.x; a[4*q+1] = v.y; a[4*q+2] = v.z; a[4*q+3] = v.w;
        }
    }

    // State: quaternion P (w,x,y,z) and position p.
    float Pw = 1.f, Px = 0.f, Py = 0.f, Pz = 0.f;
    float px = 0.f, py = 0.f, pz = 0.f;
    float* swarp = sbuf + warp * WSTG;
    const float4* kc = reinterpret_cast<const float4*>(kjc);

    // Staging write: (local col lc, row lane) -> lanes consecutive.
    #define SO(lc) swarp[(lc) * SW + lane]

    // One joint step: advance position, then quaternion (skip quat at j=23).
    #define STEP(j)                                                           \
    {                                                                         \
        const float4 wv = kc[2*(j)];                                          \
        const float4 bv = kc[2*(j) + 1];                                      \
        const float tx = Py*bv.z - Pz*bv.y;                                   \
        const float ty = Pz*bv.x - Px*bv.z;                                   \
        const float tz = Px*bv.y - Py*bv.x;                                   \
        const float w2 = Pw + Pw;                                             \
        const float ox = Py*tz - Pz*ty;                                       \
        const float oy = Pz*tx - Px*tz;                                       \
        const float oz = Px*ty - Py*tx;                                       \
        px += bv.x + w2*tx + 2.f*ox;                                          \
        py += bv.y + w2*ty + 2.f*oy;                                          \
        pz += bv.z + w2*tz + 2.f*oz;                                          \
        if ((j) < J - 1) {                                                    \
            float s_, c_;                                                     \
            __sincosf(0.5f * a[(j)], &s_, &c_);                               \
            const float qx = s_*wv.x, qy = s_*wv.y, qz = s_*wv.z;             \
            const float nw = Pw*c_ - Px*qx - Py*qy - Pz*qz;                   \
            const float nx = Pw*qx + Px*c_ + Py*qz - Pz*qy;                   \
            const float ny = Pw*qy - Px*qz + Py*c_ + Pz*qx;                   \
            const float nz = Pw*qz + Px*qy - Py*qx + Pz*c_;                   \
            Pw = nw; Px = nx; Py = ny; Pz = nz;                               \
        }                                                                     \
    }

    // Warp-private flush of NC cols at output offset `off`:
    // iter r: LDS.32 (col=lane, row=r; stride 33, conflict-free) +
    //         STG.32 (row r, cols off..off+NC) — both immediate offsets.
    #define FLUSH(off, NC)                                                    \
    {                                                                         \
        __syncwarp();                                                         \
        const float* src_ = swarp + lane * SW;                                \
        float* dst_ = gout + (warp * 32) * 75 + (off) + lane;                 \
        if (full) {                                                           \
            _Pragma("unroll")                                                 \
            for (int r = 0; r < 32; ++r)                                      \
                if (lane < (NC)) dst_[r * 75] = src_[r];                      \
        } else {                                                              \
            _Pragma("unroll")                                                 \
            for (int r = 0; r < 32; ++r)                                      \
                if (lane < (NC) && warp * 32 + r < nvalid)                    \
                    dst_[r * 75] = src_[r];                                   \
        }                                                                     \
        __syncwarp();                                                         \
    }

    __syncthreads();   // kjc ready

    // ---- Phase 0: cols [0,32) = base(0..2) + j0..8 + j9(px,py) ----
    if (active) {
        SO(0) = 0.f; SO(1) = 0.f; SO(2) = 0.f;
        #pragma unroll
        for (int j = 0; j <= 8; ++j) {
            STEP(j);
            SO(3 + 3*j) = px; SO(4 + 3*j) = py; SO(5 + 3*j) = pz;
        }
        STEP(9);
        SO(30) = px; SO(31) = py;          // col 32 (pz) deferred
    }
    FLUSH(0, 32);

    // ---- Phase 1: cols [32,64) = j9.pz + j10..19 + j20(px) ----
    if (active) {
        SO(0) = pz;                        // col 32
        #pragma unroll
        for (int j = 10; j <= 19; ++j) {
            STEP(j);
            const int lc = 3 + 3*j - 32;
            SO(lc) = px; SO(lc + 1) = py; SO(lc + 2) = pz;
        }
        STEP(20);
        SO(31) = px;                       // col 63; 64,65 deferred
    }
    FLUSH(32, 32);

    // ---- Phase 2: cols [64,75) = j20(py,pz) + j21..23 (11 cols) ----
    if (active) {
        SO(0) = py; SO(1) = pz;            // cols 64, 65
        #pragma unroll
        for (int j = 21; j <= 23; ++j) {
            STEP(j);
            const int lc = 3 + 3*j - 64;
            SO(lc) = px; SO(lc + 1) = py; SO(lc + 2) = pz;
        }
    }
    FLUSH(64, 11);

    #undef SO
    #undef STEP
    #undef FLUSH
}

extern "C" void kernel_launch(void* const* d_in, const int* in_sizes, int n_in,
                              void* d_out, int out_size) {
    const float* angles = (const float*)d_in[0];   // [B, 24]
    const float* Torg   = (const float*)d_in[1];   // [24, 4, 4]
    const float* axes   = (const float*)d_in[2];   // [24, 3]
    float* out = (float*)d_out;                    // [B, 75]

    const int B = in_sizes[0] / J;
    const int blocks = (B + TPB - 1) / TPB;
    fk_kernel<<<blocks, TPB>>>(angles, Torg, axes, out, B);
}